// round 14
// baseline (speedup 1.0000x reference)
#include <cuda_runtime.h>
#include <cuda_fp16.h>
#include <math.h>
#include <stdint.h>

#define NTOK 16384
#define NMASK 16383
#define CDIM 512
#define CFFD 2048

typedef __half half_t;

// ---------------- scratch (static device globals; no allocs) ----------------
__device__ float g_h[NTOK * CDIM];
__device__ float g_mod[8 * 3072];   // all 8 layers' adaLN modulation
__device__ float g_siluc[CDIM];
__device__ half_t g_hn[NTOK * CDIM];
__device__ half_t g_qkv[NTOK * 3 * CDIM];
__device__ half_t g_attn[NTOK * CDIM];
__device__ half_t g_mlp[NTOK * CFFD];
// weights fp16: [qkv | proj | fc1 | fc2]
#define OFF_QKV 0
#define OFF_PROJ 6291456
#define OFF_FC1 8388608
#define OFF_FC2 16777216
__device__ half_t g_w[25165824];

// ======================= helpers ============================================
#define MMA16816(acc, a, b0v, b1v)                                              \
    asm volatile(                                                               \
        "mma.sync.aligned.m16n8k16.row.col.f32.f16.f16.f32 "                    \
        "{%0,%1,%2,%3},{%4,%5,%6,%7},{%8,%9},{%0,%1,%2,%3};"                    \
        : "+f"((acc)[0]), "+f"((acc)[1]), "+f"((acc)[2]), "+f"((acc)[3])        \
        : "r"((a)[0]), "r"((a)[1]), "r"((a)[2]), "r"((a)[3]), "r"(b0v), "r"(b1v))

#define LDSM4(r0, r1, r2, r3, addr)                                             \
    asm volatile("ldmatrix.sync.aligned.m8n8.x4.shared.b16 {%0,%1,%2,%3}, [%4];" \
        : "=r"(r0), "=r"(r1), "=r"(r2), "=r"(r3) : "r"(addr))

#define CP_ASYNC16(dst_u32, src_ptr) \
    asm volatile("cp.async.cg.shared.global [%0], [%1], 16;" :: "r"(dst_u32), "l"(src_ptr))
#define CP_COMMIT() asm volatile("cp.async.commit_group;")
#define CP_WAIT1() asm volatile("cp.async.wait_group 1;")

__device__ __forceinline__ uint32_t smem_u32(const void* p) {
    uint32_t a;
    asm("{ .reg .u64 t; cvta.to.shared.u64 t, %1; cvt.u32.u64 %0, t; }" : "=r"(a) : "l"(p));
    return a;
}

__device__ __forceinline__ uint32_t pack2(float a, float b) {
    __half2 h = __floats2half2_rn(a, b);
    return *(uint32_t*)&h;
}

// fp32 -> fp16 conversion, all 4 weight tensors in ONE launch.
// Segment sizes (in float4 units) are exact multiples of 256, so no bounds checks.
// blocks: qkv 6144 | proj 2048 | fc1 8192 | fc2 8192  (total 24576)
__global__ void k_half_all(const float* __restrict__ s_qkv, const float* __restrict__ s_proj,
                           const float* __restrict__ s_fc1, const float* __restrict__ s_fc2,
                           half_t* __restrict__ dst) {
    int b = blockIdx.x;
    const float* src;
    half_t* d;
    if (b < 6144) {
        src = s_qkv; d = dst + OFF_QKV;
    } else if (b < 8192) {
        src = s_proj; d = dst + OFF_PROJ; b -= 6144;
    } else if (b < 16384) {
        src = s_fc1; d = dst + OFF_FC1; b -= 8192;
    } else {
        src = s_fc2; d = dst + OFF_FC2; b -= 16384;
    }
    int i = b * 256 + threadIdx.x;
    float4 v = ((const float4*)src)[i];
    uint2 o;
    o.x = pack2(v.x, v.y);
    o.y = pack2(v.z, v.w);
    ((uint2*)d)[i] = o;
}

// ======================= fp16 HMMA GEMM (cp.async 3-stage, ldmatrix) ========
// out(NxM) = A(NxK) @ W(MxK)^T; fp16 operands, fp32 acc.
// CTA 128x128, BK=32, 8 warps (2x4), warp tile 64x32, 2 CTAs/SM.
// EPI 0: half-write (qkv; scale 0.125 on cols<512)
// EPI 1: gelu then half-write
// EPI 2: outf += gate[col]*(acc+bias)   (fp32 RMW)
template <int EPI>
__global__ void __launch_bounds__(256, 2)
k_mma_gemm(const half_t* __restrict__ A, const half_t* __restrict__ W,
           const float* __restrict__ bias, float* __restrict__ outf,
           half_t* __restrict__ oh, const float* __restrict__ gate, int K, int M) {
    extern __shared__ uint32_t smw[];  // 3 stages x (A+B) x 2560 words = 61440B

    const int tid = threadIdx.x;
    const int wid = tid >> 5;
    const int lane = tid & 31;
    const int g = lane >> 2;
    const int t = lane & 3;
    const int warp_m = wid >> 2;
    const int warp_n = wid & 3;
    const int lq = lane >> 3, lr = lane & 7;

    const int m0 = blockIdx.y * 128;
    const int n0 = blockIdx.x * 128;

    const half_t* Ap = A + (long)m0 * K;
    const half_t* Bp = W + (long)n0 * K;
    const int NC = K >> 5;

    const uint32_t sbase = smem_u32(smw);
    const int cr = tid >> 2, cq = tid & 3;

    // ldmatrix per-lane role constants (words)
    const int a_row = warp_m * 64 + lr + ((lq & 1) << 3);  // + mt*16
    const int a_koff = (lq >> 1) << 2;                     // + ks*8
    const int b_col = warp_n * 32 + ((lq >> 1) << 3) + lr; // + j*16
    const int b_koff = (lq & 1) << 2;                      // + ks*8

    float acc[4][4][4];
#pragma unroll
    for (int i = 0; i < 4; i++)
#pragma unroll
        for (int j = 0; j < 4; j++)
#pragma unroll
            for (int k = 0; k < 4; k++) acc[i][j][k] = 0.f;

    // issue cp.async for chunk c into stage s (each thread: 4 x 16B)
    auto cp_chunk = [&](int c, int s) {
        uint32_t st = sbase + s * 20480;
#pragma unroll
        for (int it = 0; it < 2; it++) {
            int r = cr + it * 64;
            long go = (long)r * K + c * 32 + cq * 8;
            uint32_t so = st + (uint32_t)(r * 80 + cq * 16);
            CP_ASYNC16(so, Ap + go);
            CP_ASYNC16(so + 10240, Bp + go);
        }
    };

    auto compute = [&](int s) {
        uint32_t stA = sbase + s * 20480;
        uint32_t stB = stA + 10240;
#pragma unroll
        for (int ks = 0; ks < 2; ks++) {
            uint32_t a[4][4], b[4][2];
#pragma unroll
            for (int mt = 0; mt < 4; mt++) {
                uint32_t ad = stA + (uint32_t)(((a_row + mt * 16) * 20 + a_koff + ks * 8) * 4);
                LDSM4(a[mt][0], a[mt][1], a[mt][2], a[mt][3], ad);
            }
#pragma unroll
            for (int j = 0; j < 2; j++) {
                uint32_t bd = stB + (uint32_t)(((b_col + j * 16) * 20 + b_koff + ks * 8) * 4);
                LDSM4(b[2 * j][0], b[2 * j][1], b[2 * j + 1][0], b[2 * j + 1][1], bd);
            }
#pragma unroll
            for (int nt = 0; nt < 4; nt++)
#pragma unroll
                for (int mt = 0; mt < 4; mt++)
                    MMA16816(acc[mt][nt], a[mt], b[nt][0], b[nt][1]);
        }
    };

    cp_chunk(0, 0); CP_COMMIT();
    cp_chunk(1, 1); CP_COMMIT();

    int s_next = 2, s_cur = 0;
    for (int c = 0; c < NC; c++) {
        CP_WAIT1();
        __syncthreads();
        if (c + 2 < NC) cp_chunk(c + 2, s_next);
        CP_COMMIT();
        compute(s_cur);
        s_cur = (s_cur == 2) ? 0 : s_cur + 1;
        s_next = (s_next == 2) ? 0 : s_next + 1;
    }

    // ---- epilogue ----
#pragma unroll
    for (int mt = 0; mt < 4; mt++) {
#pragma unroll
        for (int nt = 0; nt < 4; nt++) {
            float* ac = acc[mt][nt];
            int row = m0 + warp_m * 64 + mt * 16 + g;
            int col = n0 + warp_n * 32 + nt * 8 + 2 * t;
            float b0 = __ldg(bias + col), b1 = __ldg(bias + col + 1);
            float v[4];
            v[0] = ac[0] + b0; v[1] = ac[1] + b1;
            v[2] = ac[2] + b0; v[3] = ac[3] + b1;
            if (EPI == 0) {
                if (col < 512) {
#pragma unroll
                    for (int e = 0; e < 4; e++) v[e] *= 0.125f;
                }
            }
            if (EPI == 1) {
#pragma unroll
                for (int e = 0; e < 4; e++) {
                    float x = v[e];
                    float x3 = x * x * x;
                    v[e] = 0.5f * x * (1.0f + tanhf(0.7978845608028654f * (x + 0.044715f * x3)));
                }
            }
            if (EPI == 2) {
                float* dp0 = outf + (long)row * M + col;
                float* dp1 = outf + (long)(row + 8) * M + col;
                float g0 = __ldg(gate + col), g1 = __ldg(gate + col + 1);
                float2 o0 = *(float2*)dp0;
                float2 o1 = *(float2*)dp1;
                o0.x += g0 * v[0]; o0.y += g1 * v[1];
                o1.x += g0 * v[2]; o1.y += g1 * v[3];
                *(float2*)dp0 = o0;
                *(float2*)dp1 = o1;
            } else {
                *(uint32_t*)(oh + (long)row * M + col) = pack2(v[0], v[1]);
                *(uint32_t*)(oh + (long)(row + 8) * M + col) = pack2(v[2], v[3]);
            }
        }
    }
}

// ======================= fp16 HMMA windowed flash attention =================
// grid (qtile=8, head=8, window=16), 256 thr (8 warps), BQ=128, BKV=64, D=64.
// q pre-scaled by 0.125 at the qkv epilogue. ldmatrix frag loads, occupancy 1.
// K/V for chunk c+1 are prefetched into REGISTERS during chunk c's compute,
// so global-load latency is hidden; only reg->smem stores sit between syncs.
__global__ void __launch_bounds__(256, 1)
k_attn_mma(const half_t* __restrict__ qkv, half_t* __restrict__ attn, int shift) {
    extern __shared__ uint32_t sw[];
    uint32_t* Qs = sw;            // 128 rows x 36 words (72 half pitch)
    uint32_t* Ks = Qs + 4608;     // 64 rows x 36 words
    uint32_t* Vs = Ks + 2304;     // 64 d-rows x 36 words (token-pair packed)

    const int tid = threadIdx.x;
    const int wid = tid >> 5;
    const int lane = tid & 31;
    const int g = lane >> 2;
    const int t = tid & 3;

    const int lq = lane >> 3, lr = lane & 7;

    const int qt = blockIdx.x, hh = blockIdx.y, w = blockIdx.z;
    const int qbase = w * 1024 + qt * 128;
    const int r0 = wid * 16;

    const uint32_t sbase = smem_u32(sw);
    // ldmatrix lane addresses (bytes); += ks*32 / kt*32 per step
    const uint32_t q_ad = sbase + (uint32_t)(((r0 + lr + ((lane & 8) ? 8 : 0)) * 36 + ((lq >> 1) << 2)) * 4);
    const uint32_t kv_row = (uint32_t)((((lq >> 1) << 3) + lr) * 36 + ((lq & 1) << 2)) * 4;
    const uint32_t k_ad = sbase + 18432 + kv_row;
    const uint32_t v_ad = sbase + 27648 + kv_row;

    // per-thread load roles
    const int jr = tid >> 2, qf = tid & 3;      // K copy: row jr, 16-half group qf
    const int jp = tid & 31, dg = tid >> 5;     // V pack: token-pair jp, d-group dg

    // ---- load Q tile ----
    {
        int row = tid >> 1, hf = tid & 1;
        int tok = (qbase + row + shift) & NMASK;
        const uint4* p = (const uint4*)(qkv + (long)tok * 1536 + hh * 64 + hf * 32);
        int wo = row * 36 + hf * 16;
#pragma unroll
        for (int q = 0; q < 4; q++) *(uint4*)&Qs[wo + q * 4] = p[q];
    }

    // ---- K/V register prefetch ----
    uint4 kr0, kr1, vr0, vr1;
    auto load_kv = [&](int c) {
        int j0 = c * 64;
        int tokk = (w * 1024 + j0 + jr + shift) & NMASK;
        const uint4* p = (const uint4*)(qkv + (long)tokk * 1536 + 512 + hh * 64 + qf * 16);
        kr0 = p[0];
        kr1 = p[1];
        int t0 = (w * 1024 + j0 + 2 * jp + shift) & NMASK;
        int t1 = (w * 1024 + j0 + 2 * jp + 1 + shift) & NMASK;
        vr0 = *(const uint4*)(qkv + (long)t0 * 1536 + 1024 + hh * 64 + dg * 8);
        vr1 = *(const uint4*)(qkv + (long)t1 * 1536 + 1024 + hh * 64 + dg * 8);
    };

    load_kv(0);  // prefetch chunk 0

    float accO[8][4];
#pragma unroll
    for (int i = 0; i < 8; i++)
#pragma unroll
        for (int j = 0; j < 4; j++) accO[i][j] = 0.f;
    float m0 = -1e30f, m1 = -1e30f, l0 = 0.f, l1 = 0.f;

    for (int c = 0; c < 16; c++) {
        __syncthreads();  // previous chunk's consumers done; smem free
        // store prefetched K
        {
            int wo = jr * 36 + qf * 8;
            *(uint4*)&Ks[wo] = kr0;
            *(uint4*)&Ks[wo + 4] = kr1;
        }
        // pack + store prefetched V (transpose-pack Vt[d][token-pair])
        {
            const half_t* a0 = (const half_t*)&vr0;
            const half_t* a1 = (const half_t*)&vr1;
#pragma unroll
            for (int i = 0; i < 8; i++) {
                uint32_t pv;
                ((half_t*)&pv)[0] = a0[i];
                ((half_t*)&pv)[1] = a1[i];
                Vs[(dg * 8 + i) * 36 + jp] = pv;
            }
        }
        __syncthreads();  // smem ready

        if (c + 1 < 16) load_kv(c + 1);  // LDG latency overlaps compute below

        // ---- S = Q K^T (16x64 per warp), ldmatrix frags ----
        float accS[8][4];
#pragma unroll
        for (int i = 0; i < 8; i++)
#pragma unroll
            for (int j = 0; j < 4; j++) accS[i][j] = 0.f;
#pragma unroll
        for (int ks = 0; ks < 4; ks++) {
            uint32_t a[4];
            LDSM4(a[0], a[1], a[2], a[3], q_ad + ks * 32);
#pragma unroll
            for (int j = 0; j < 4; j++) {
                uint32_t b[4];
                LDSM4(b[0], b[1], b[2], b[3], k_ad + (uint32_t)(j * 16 * 144) + ks * 32);
                MMA16816(accS[2 * j], a, b[0], b[1]);
                MMA16816(accS[2 * j + 1], a, b[2], b[3]);
            }
        }

        // ---- online softmax ----
        float ml0 = -1e30f, ml1 = -1e30f;
#pragma unroll
        for (int nt = 0; nt < 8; nt++) {
            ml0 = fmaxf(ml0, fmaxf(accS[nt][0], accS[nt][1]));
            ml1 = fmaxf(ml1, fmaxf(accS[nt][2], accS[nt][3]));
        }
#pragma unroll
        for (int off = 1; off < 4; off <<= 1) {
            ml0 = fmaxf(ml0, __shfl_xor_sync(0xffffffffu, ml0, off));
            ml1 = fmaxf(ml1, __shfl_xor_sync(0xffffffffu, ml1, off));
        }
        float mn0 = fmaxf(m0, ml0), mn1 = fmaxf(m1, ml1);
        float alpha0 = __expf(m0 - mn0), alpha1 = __expf(m1 - mn1);
        m0 = mn0; m1 = mn1;
        float rs0 = 0.f, rs1 = 0.f;
#pragma unroll
        for (int nt = 0; nt < 8; nt++) {
            accS[nt][0] = __expf(accS[nt][0] - mn0);
            accS[nt][1] = __expf(accS[nt][1] - mn0);
            accS[nt][2] = __expf(accS[nt][2] - mn1);
            accS[nt][3] = __expf(accS[nt][3] - mn1);
            rs0 += accS[nt][0] + accS[nt][1];
            rs1 += accS[nt][2] + accS[nt][3];
        }
#pragma unroll
        for (int off = 1; off < 4; off <<= 1) {
            rs0 += __shfl_xor_sync(0xffffffffu, rs0, off);
            rs1 += __shfl_xor_sync(0xffffffffu, rs1, off);
        }
        l0 = l0 * alpha0 + rs0;
        l1 = l1 * alpha1 + rs1;
#pragma unroll
        for (int nt = 0; nt < 8; nt++) {
            accO[nt][0] *= alpha0; accO[nt][1] *= alpha0;
            accO[nt][2] *= alpha1; accO[nt][3] *= alpha1;
        }

        // ---- O += P V (P in regs, V via ldmatrix) ----
#pragma unroll
        for (int kt = 0; kt < 4; kt++) {
            uint32_t p[4];
            p[0] = pack2(accS[2 * kt][0], accS[2 * kt][1]);
            p[1] = pack2(accS[2 * kt][2], accS[2 * kt][3]);
            p[2] = pack2(accS[2 * kt + 1][0], accS[2 * kt + 1][1]);
            p[3] = pack2(accS[2 * kt + 1][2], accS[2 * kt + 1][3]);
#pragma unroll
            for (int j = 0; j < 4; j++) {
                uint32_t b[4];
                LDSM4(b[0], b[1], b[2], b[3], v_ad + (uint32_t)(j * 16 * 144) + kt * 32);
                MMA16816(accO[2 * j], p, b[0], b[1]);
                MMA16816(accO[2 * j + 1], p, b[2], b[3]);
            }
        }
    }

    // ---- finalize + write ----
    float inv0 = 1.0f / l0, inv1 = 1.0f / l1;
    int tokA = (qbase + r0 + g + shift) & NMASK;
    int tokB = (qbase + r0 + g + 8 + shift) & NMASK;
#pragma unroll
    for (int nt = 0; nt < 8; nt++) {
        int col = hh * 64 + nt * 8 + 2 * t;
        *(uint32_t*)(attn + (long)tokA * CDIM + col) = pack2(accO[nt][0] * inv0, accO[nt][1] * inv0);
        *(uint32_t*)(attn + (long)tokB * CDIM + col) = pack2(accO[nt][2] * inv1, accO[nt][3] * inv1);
    }
}

// ---------------- input embed ------------------------------------------------
__global__ void k_init(const float* __restrict__ feats, const int* __restrict__ coords,
                       const float* __restrict__ in_w, const float* __restrict__ in_b,
                       float* __restrict__ h) {
    int n = blockIdx.x;
    int tid = threadIdx.x;  // 256
    __shared__ float f[8];
    __shared__ int cd[3];
    if (tid < 8) f[tid] = feats[n * 8 + tid];
    if (tid < 3) cd[tid] = coords[n * 3 + tid];
    __syncthreads();
    for (int c = tid; c < CDIM; c += 256) {
        float acc = in_b[c];
#pragma unroll
        for (int i = 0; i < 8; i++) acc += f[i] * in_w[c * 8 + i];
        if (c < 510) {
            int j = c / 170;
            int k = c - j * 170;
            int kk = (k < 85) ? k : k - 85;
            float freq = expf((float)kk * (-9.210340371976184f / 85.0f));
            float o = (float)cd[j] * freq;
            acc += (k < 85) ? sinf(o) : cosf(o);
        }
        h[(long)n * CDIM + c] = acc;
    }
}

// ---------------- t embedding -> silu(c) ------------------------------------
__global__ void k_tembed(const float* __restrict__ t,
                         const float* __restrict__ w1, const float* __restrict__ b1,
                         const float* __restrict__ w2, const float* __restrict__ b2,
                         float* __restrict__ siluc) {
    __shared__ float emb[256];
    __shared__ float hid[512];
    int tid = threadIdx.x;  // 256
    float tv = t[0];
    if (tid < 128) {
        float fr = expf((float)tid * (-9.210340371976184f / 128.0f));
        float a = tv * fr;
        emb[tid] = cosf(a);
        emb[128 + tid] = sinf(a);
    }
    __syncthreads();
    for (int c = tid; c < 512; c += 256) {
        float acc = b1[c];
        const float* wr = w1 + (long)c * 256;
        for (int k = 0; k < 256; k++) acc += emb[k] * wr[k];
        hid[c] = acc / (1.0f + expf(-acc));
    }
    __syncthreads();
    for (int c = tid; c < 512; c += 256) {
        float acc = b2[c];
        const float* wr = w2 + (long)c * 512;
        for (int k = 0; k < 512; k++) acc += hid[k] * wr[k];
        siluc[c] = acc / (1.0f + expf(-acc));
    }
}

// ---------------- adaLN modulation: ALL 8 layers in one launch ---------------
__global__ void k_ada(const float* __restrict__ siluc, const float* __restrict__ ada_w,
                      const float* __restrict__ ada_b, float* __restrict__ mod) {
    __shared__ float sc[512];
    int tid = threadIdx.x;  // 256
    for (int c = tid; c < 512; c += 256) sc[c] = siluc[c];
    __syncthreads();
    int warp = tid >> 5, lane = tid & 31;
    int m = blockIdx.x * 8 + warp;  // 0..24575
    const float* wr = ada_w + (long)m * 512;
    float acc = 0.f;
    for (int k = lane; k < 512; k += 32) acc += sc[k] * wr[k];
#pragma unroll
    for (int off = 16; off; off >>= 1) acc += __shfl_xor_sync(0xffffffffu, acc, off);
    if (lane == 0) mod[m] = acc + ada_b[m];
}

// ---------------- LN + modulation -> fp16 ------------------------------------
__global__ void k_modln(const float* __restrict__ h, half_t* __restrict__ hn,
                        const float* __restrict__ mod, int sc_off, int sm_off) {
    int n = blockIdx.x;
    int tid = threadIdx.x;  // 128
    const float4* hp = (const float4*)(h + (long)n * CDIM);
    float4 x = hp[tid];
    float s = x.x + x.y + x.z + x.w;
    float sq = x.x * x.x + x.y * x.y + x.z * x.z + x.w * x.w;
#pragma unroll
    for (int off = 16; off; off >>= 1) {
        s += __shfl_xor_sync(0xffffffffu, s, off);
        sq += __shfl_xor_sync(0xffffffffu, sq, off);
    }
    __shared__ float rs[4], rq[4];
    int warp = tid >> 5;
    if ((tid & 31) == 0) { rs[warp] = s; rq[warp] = sq; }
    __syncthreads();
    float S = rs[0] + rs[1] + rs[2] + rs[3];
    float SQ = rq[0] + rq[1] + rq[2] + rq[3];
    float mean = S * (1.0f / 512.0f);
    float var = SQ * (1.0f / 512.0f) - mean * mean;
    float inv = rsqrtf(var + 1e-6f);
    int c = tid * 4;
    float4 scv = *(const float4*)(mod + sc_off + c);
    float4 smv = *(const float4*)(mod + sm_off + c);
    float o0 = (x.x - mean) * inv * (1.0f + scv.x) + smv.x;
    float o1 = (x.y - mean) * inv * (1.0f + scv.y) + smv.y;
    float o2 = (x.z - mean) * inv * (1.0f + scv.z) + smv.z;
    float o3 = (x.w - mean) * inv * (1.0f + scv.w) + smv.w;
    uint2 o;
    o.x = pack2(o0, o1);
    o.y = pack2(o2, o3);
    *(uint2*)(hn + (long)n * CDIM + c) = o;
}

// ---------------- output head ------------------------------------------------
__global__ void k_final(const float* __restrict__ h, const float* __restrict__ out_w,
                        const float* __restrict__ out_b, float* __restrict__ out) {
    int warp = threadIdx.x >> 5, lane = threadIdx.x & 31;
    int n = blockIdx.x * 8 + warp;
    const float* hp = h + (long)n * CDIM;
    float acc[8];
#pragma unroll
    for (int o = 0; o < 8; o++) acc[o] = 0.f;
    for (int c = lane; c < CDIM; c += 32) {
        float hv = hp[c];
#pragma unroll
        for (int o = 0; o < 8; o++) acc[o] += hv * out_w[o * CDIM + c];
    }
#pragma unroll
    for (int off = 16; off; off >>= 1)
#pragma unroll
        for (int o = 0; o < 8; o++) acc[o] += __shfl_xor_sync(0xffffffffu, acc[o], off);
    if (lane == 0)
#pragma unroll
        for (int o = 0; o < 8; o++) out[(long)n * 8 + o] = acc[o] + out_b[o];
}

// ---------------- launch ----------------------------------------------------
extern "C" void kernel_launch(void* const* d_in, const int* in_sizes, int n_in,
                              void* d_out, int out_size) {
    const float* feats  = (const float*)d_in[0];
    const int*   coords = (const int*)d_in[1];
    const float* t      = (const float*)d_in[2];
    const float* in_w   = (const float*)d_in[3];
    const float* in_b   = (const float*)d_in[4];
    const float* t_w1   = (const float*)d_in[5];
    const float* t_b1   = (const float*)d_in[6];
    const float* t_w2   = (const float*)d_in[7];
    const float* t_b2   = (const float*)d_in[8];
    const float* qkv_w  = (const float*)d_in[9];
    const float* qkv_b  = (const float*)d_in[10];
    const float* proj_w = (const float*)d_in[11];
    const float* proj_b = (const float*)d_in[12];
    const float* ada_w  = (const float*)d_in[13];
    const float* ada_b  = (const float*)d_in[14];
    const float* fc1_w  = (const float*)d_in[15];
    const float* fc1_b  = (const float*)d_in[16];
    const float* fc2_w  = (const float*)d_in[17];
    const float* fc2_b  = (const float*)d_in[18];
    const float* out_w  = (const float*)d_in[19];
    const float* out_b  = (const float*)d_in[20];
    float* out = (float*)d_out;

    float *p_h, *p_mod, *p_siluc;
    half_t *p_hn, *p_q, *p_a, *p_m, *p_w;
    cudaGetSymbolAddress((void**)&p_h, g_h);
    cudaGetSymbolAddress((void**)&p_mod, g_mod);
    cudaGetSymbolAddress((void**)&p_siluc, g_siluc);
    cudaGetSymbolAddress((void**)&p_hn, g_hn);
    cudaGetSymbolAddress((void**)&p_q, g_qkv);
    cudaGetSymbolAddress((void**)&p_a, g_attn);
    cudaGetSymbolAddress((void**)&p_m, g_mlp);
    cudaGetSymbolAddress((void**)&p_w, g_w);

    const int GSM = 61440;  // 3 stages x 20480B
    const int ASM = 36864;  // Q 4608 + K 2304 + V 2304 words
    cudaFuncSetAttribute(k_mma_gemm<0>, cudaFuncAttributeMaxDynamicSharedMemorySize, GSM);
    cudaFuncSetAttribute(k_mma_gemm<1>, cudaFuncAttributeMaxDynamicSharedMemorySize, GSM);
    cudaFuncSetAttribute(k_mma_gemm<2>, cudaFuncAttributeMaxDynamicSharedMemorySize, GSM);
    cudaFuncSetAttribute(k_attn_mma, cudaFuncAttributeMaxDynamicSharedMemorySize, ASM);

    // weight fp16 conversion — single launch covering all 4 tensors
    k_half_all<<<24576, 256>>>(qkv_w, proj_w, fc1_w, fc2_w, p_w);

    k_init<<<NTOK, 256>>>(feats, coords, in_w, in_b, p_h);
    k_tembed<<<1, 256>>>(t, t_w1, t_b1, t_w2, t_b2, p_siluc);
    // all 8 layers' adaLN modulation upfront (loop-invariant)
    k_ada<<<3072, 256>>>(p_siluc, ada_w, ada_b, p_mod);

    for (int i = 0; i < 8; i++) {
        int shift = (i & 1) * 512;
        const float* mod_i = p_mod + i * 3072;
        // attention branch
        k_modln<<<NTOK, 128>>>(p_h, p_hn, mod_i, 512, 0);
        k_mma_gemm<0><<<dim3(12, 128), 256, GSM>>>(
            p_hn, p_w + OFF_QKV + (long)i * 786432, qkv_b + (long)i * 1536,
            nullptr, p_q, nullptr, 512, 1536);
        k_attn_mma<<<dim3(8, 8, 16), 256, ASM>>>(p_q, p_a, shift);
        k_mma_gemm<2><<<dim3(4, 128), 256, GSM>>>(
            p_a, p_w + OFF_PROJ + (long)i * 262144, proj_b + (long)i * 512,
            p_h, nullptr, mod_i + 1024, 512, 512);
        // mlp branch
        k_modln<<<NTOK, 128>>>(p_h, p_hn, mod_i, 2048, 1536);
        k_mma_gemm<1><<<dim3(16, 128), 256, GSM>>>(
            p_hn, p_w + OFF_FC1 + (long)i * 1048576, fc1_b + (long)i * 2048,
            nullptr, p_m, nullptr, 512, 2048);
        k_mma_gemm<2><<<dim3(4, 128), 256, GSM>>>(
            p_m, p_w + OFF_FC2 + (long)i * 1048576, fc2_b + (long)i * 512,
            p_h, nullptr, mod_i + 2560, 2048, 512);
    }

    k_final<<<2048, 256>>>(p_h, out_w, out_b, out);
}

// round 15
// speedup vs baseline: 1.0371x; 1.0371x over previous
#include <cuda_runtime.h>
#include <cuda_fp16.h>
#include <math.h>
#include <stdint.h>

#define NTOK 16384
#define NMASK 16383
#define CDIM 512
#define CFFD 2048

typedef __half half_t;

// ---------------- scratch (static device globals; no allocs) ----------------
__device__ float g_h[NTOK * CDIM];
__device__ float g_mod[8 * 3072];   // all 8 layers' adaLN modulation
__device__ float g_siluc[CDIM];
__device__ half_t g_hn[NTOK * CDIM];
__device__ half_t g_qkv[NTOK * 3 * CDIM];
__device__ half_t g_attn[NTOK * CDIM];
__device__ half_t g_mlp[NTOK * CFFD];
// weights fp16: [qkv | proj | fc1 | fc2]
#define OFF_QKV 0
#define OFF_PROJ 6291456
#define OFF_FC1 8388608
#define OFF_FC2 16777216
__device__ half_t g_w[25165824];

// ======================= helpers ============================================
// fp16-accumulate mma: D,C are 2 regs of f16x2 (row g | row g+8)
#define MMA16816H(c0, c1, a, b0v, b1v)                                          \
    asm volatile(                                                               \
        "mma.sync.aligned.m16n8k16.row.col.f16.f16.f16.f16 "                    \
        "{%0,%1},{%2,%3,%4,%5},{%6,%7},{%0,%1};"                                \
        : "+r"(c0), "+r"(c1)                                                    \
        : "r"((a)[0]), "r"((a)[1]), "r"((a)[2]), "r"((a)[3]), "r"(b0v), "r"(b1v))

#define LDSM4(r0, r1, r2, r3, addr)                                             \
    asm volatile("ldmatrix.sync.aligned.m8n8.x4.shared.b16 {%0,%1,%2,%3}, [%4];" \
        : "=r"(r0), "=r"(r1), "=r"(r2), "=r"(r3) : "r"(addr))

#define CP_ASYNC16(dst_u32, src_ptr) \
    asm volatile("cp.async.cg.shared.global [%0], [%1], 16;" :: "r"(dst_u32), "l"(src_ptr))
#define CP_COMMIT() asm volatile("cp.async.commit_group;")
#define CP_WAIT1() asm volatile("cp.async.wait_group 1;")

__device__ __forceinline__ uint32_t smem_u32(const void* p) {
    uint32_t a;
    asm("{ .reg .u64 t; cvta.to.shared.u64 t, %1; cvt.u32.u64 %0, t; }" : "=r"(a) : "l"(p));
    return a;
}

__device__ __forceinline__ uint32_t pack2(float a, float b) {
    __half2 h = __floats2half2_rn(a, b);
    return *(uint32_t*)&h;
}
__device__ __forceinline__ float2 unpack2(uint32_t v) {
    __half2 h = *(__half2*)&v;
    return make_float2(__half2float(h.x), __half2float(h.y));
}

// fp32 -> fp16 conversion, all 4 weight tensors in ONE launch.
__global__ void k_half_all(const float* __restrict__ s_qkv, const float* __restrict__ s_proj,
                           const float* __restrict__ s_fc1, const float* __restrict__ s_fc2,
                           half_t* __restrict__ dst) {
    int b = blockIdx.x;
    const float* src;
    half_t* d;
    if (b < 6144) {
        src = s_qkv; d = dst + OFF_QKV;
    } else if (b < 8192) {
        src = s_proj; d = dst + OFF_PROJ; b -= 6144;
    } else if (b < 16384) {
        src = s_fc1; d = dst + OFF_FC1; b -= 8192;
    } else {
        src = s_fc2; d = dst + OFF_FC2; b -= 16384;
    }
    int i = b * 256 + threadIdx.x;
    float4 v = ((const float4*)src)[i];
    uint2 o;
    o.x = pack2(v.x, v.y);
    o.y = pack2(v.z, v.w);
    ((uint2*)d)[i] = o;
}

// ======================= fp16 HMMA GEMM (f16 accumulate) ====================
// out(NxM) = A(NxK) @ W(MxK)^T; fp16 operands AND accumulators (2x mma rate).
// CTA 128x128, BK=32, 8 warps (2x4), warp tile 64x32, 2 CTAs/SM.
// EPI 0: half-write (qkv; scale 0.125 on cols<512)
// EPI 1: gelu then half-write
// EPI 2: outf += gate[col]*(acc+bias)   (fp32 RMW)
template <int EPI>
__global__ void __launch_bounds__(256, 2)
k_mma_gemm(const half_t* __restrict__ A, const half_t* __restrict__ W,
           const float* __restrict__ bias, float* __restrict__ outf,
           half_t* __restrict__ oh, const float* __restrict__ gate, int K, int M) {
    extern __shared__ uint32_t smw[];  // 3 stages x (A+B) x 2560 words = 61440B

    const int tid = threadIdx.x;
    const int wid = tid >> 5;
    const int lane = tid & 31;
    const int g = lane >> 2;
    const int t = lane & 3;
    const int warp_m = wid >> 2;
    const int warp_n = wid & 3;
    const int lq = lane >> 3, lr = lane & 7;

    const int m0 = blockIdx.y * 128;
    const int n0 = blockIdx.x * 128;

    const half_t* Ap = A + (long)m0 * K;
    const half_t* Bp = W + (long)n0 * K;
    const int NC = K >> 5;

    const uint32_t sbase = smem_u32(smw);
    const int cr = tid >> 2, cq = tid & 3;

    // ldmatrix per-lane role constants (words)
    const int a_row = warp_m * 64 + lr + ((lq & 1) << 3);  // + mt*16
    const int a_koff = (lq >> 1) << 2;                     // + ks*8
    const int b_col = warp_n * 32 + ((lq >> 1) << 3) + lr; // + j*16
    const int b_koff = (lq & 1) << 2;                      // + ks*8

    uint32_t acc[4][4][2];  // f16x2 accumulators: [mt][nt][row g | row g+8]
#pragma unroll
    for (int i = 0; i < 4; i++)
#pragma unroll
        for (int j = 0; j < 4; j++) { acc[i][j][0] = 0u; acc[i][j][1] = 0u; }

    auto cp_chunk = [&](int c, int s) {
        uint32_t st = sbase + s * 20480;
#pragma unroll
        for (int it = 0; it < 2; it++) {
            int r = cr + it * 64;
            long go = (long)r * K + c * 32 + cq * 8;
            uint32_t so = st + (uint32_t)(r * 80 + cq * 16);
            CP_ASYNC16(so, Ap + go);
            CP_ASYNC16(so + 10240, Bp + go);
        }
    };

    auto compute = [&](int s) {
        uint32_t stA = sbase + s * 20480;
        uint32_t stB = stA + 10240;
#pragma unroll
        for (int ks = 0; ks < 2; ks++) {
            uint32_t a[4][4], b[4][2];
#pragma unroll
            for (int mt = 0; mt < 4; mt++) {
                uint32_t ad = stA + (uint32_t)(((a_row + mt * 16) * 20 + a_koff + ks * 8) * 4);
                LDSM4(a[mt][0], a[mt][1], a[mt][2], a[mt][3], ad);
            }
#pragma unroll
            for (int j = 0; j < 2; j++) {
                uint32_t bd = stB + (uint32_t)(((b_col + j * 16) * 20 + b_koff + ks * 8) * 4);
                LDSM4(b[2 * j][0], b[2 * j][1], b[2 * j + 1][0], b[2 * j + 1][1], bd);
            }
#pragma unroll
            for (int nt = 0; nt < 4; nt++)
#pragma unroll
                for (int mt = 0; mt < 4; mt++)
                    MMA16816H(acc[mt][nt][0], acc[mt][nt][1], a[mt], b[nt][0], b[nt][1]);
        }
    };

    cp_chunk(0, 0); CP_COMMIT();
    cp_chunk(1, 1); CP_COMMIT();

    int s_next = 2, s_cur = 0;
    for (int c = 0; c < NC; c++) {
        CP_WAIT1();
        __syncthreads();
        if (c + 2 < NC) cp_chunk(c + 2, s_next);
        CP_COMMIT();
        compute(s_cur);
        s_cur = (s_cur == 2) ? 0 : s_cur + 1;
        s_next = (s_next == 2) ? 0 : s_next + 1;
    }

    // ---- epilogue (fp32 math on unpacked accumulators) ----
#pragma unroll
    for (int mt = 0; mt < 4; mt++) {
#pragma unroll
        for (int nt = 0; nt < 4; nt++) {
            float2 u0 = unpack2(acc[mt][nt][0]);
            float2 u1 = unpack2(acc[mt][nt][1]);
            int row = m0 + warp_m * 64 + mt * 16 + g;
            int col = n0 + warp_n * 32 + nt * 8 + 2 * t;
            float b0 = __ldg(bias + col), b1 = __ldg(bias + col + 1);
            float v[4];
            v[0] = u0.x + b0; v[1] = u0.y + b1;
            v[2] = u1.x + b0; v[3] = u1.y + b1;
            if (EPI == 0) {
                if (col < 512) {
#pragma unroll
                    for (int e = 0; e < 4; e++) v[e] *= 0.125f;
                }
            }
            if (EPI == 1) {
#pragma unroll
                for (int e = 0; e < 4; e++) {
                    float x = v[e];
                    float x3 = x * x * x;
                    v[e] = 0.5f * x * (1.0f + tanhf(0.7978845608028654f * (x + 0.044715f * x3)));
                }
            }
            if (EPI == 2) {
                float* dp0 = outf + (long)row * M + col;
                float* dp1 = outf + (long)(row + 8) * M + col;
                float g0 = __ldg(gate + col), g1 = __ldg(gate + col + 1);
                float2 o0 = *(float2*)dp0;
                float2 o1 = *(float2*)dp1;
                o0.x += g0 * v[0]; o0.y += g1 * v[1];
                o1.x += g0 * v[2]; o1.y += g1 * v[3];
                *(float2*)dp0 = o0;
                *(float2*)dp1 = o1;
            } else {
                *(uint32_t*)(oh + (long)row * M + col) = pack2(v[0], v[1]);
                *(uint32_t*)(oh + (long)(row + 8) * M + col) = pack2(v[2], v[3]);
            }
        }
    }
}

// ======================= fp16 HMMA windowed flash attention =================
// grid (qtile=8, head=8, window=16), 256 thr (8 warps), BQ=128, BKV=64, D=64.
// q pre-scaled by 0.125 at the qkv epilogue. f16 accumulators for S and O;
// softmax stats (m, l) in fp32; alpha applied to l at fp16 precision so the
// O/l ratio cancels the rescale rounding. P needs no packing: the f16 C
// fragment layout of S IS the A fragment layout for PV.
__global__ void __launch_bounds__(256, 1)
k_attn_mma(const half_t* __restrict__ qkv, half_t* __restrict__ attn, int shift) {
    extern __shared__ uint32_t sw[];
    uint32_t* Qs = sw;            // 128 rows x 36 words (72 half pitch)
    uint32_t* Ks = Qs + 4608;     // 64 rows x 36 words
    uint32_t* Vs = Ks + 2304;     // 64 d-rows x 36 words (token-pair packed)

    const int tid = threadIdx.x;
    const int wid = tid >> 5;
    const int lane = tid & 31;
    const int g = lane >> 2;
    const int t = tid & 3;

    const int lq = lane >> 3, lr = lane & 7;

    const int qt = blockIdx.x, hh = blockIdx.y, w = blockIdx.z;
    const int qbase = w * 1024 + qt * 128;
    const int r0 = wid * 16;

    const uint32_t sbase = smem_u32(sw);
    const uint32_t q_ad = sbase + (uint32_t)(((r0 + lr + ((lane & 8) ? 8 : 0)) * 36 + ((lq >> 1) << 2)) * 4);
    const uint32_t kv_row = (uint32_t)((((lq >> 1) << 3) + lr) * 36 + ((lq & 1) << 2)) * 4;
    const uint32_t k_ad = sbase + 18432 + kv_row;
    const uint32_t v_ad = sbase + 27648 + kv_row;

    const int jr = tid >> 2, qf = tid & 3;
    const int jp = tid & 31, dg = tid >> 5;

    // ---- load Q tile ----
    {
        int row = tid >> 1, hf = tid & 1;
        int tok = (qbase + row + shift) & NMASK;
        const uint4* p = (const uint4*)(qkv + (long)tok * 1536 + hh * 64 + hf * 32);
        int wo = row * 36 + hf * 16;
#pragma unroll
        for (int q = 0; q < 4; q++) *(uint4*)&Qs[wo + q * 4] = p[q];
    }

    uint4 kr0, kr1, vr0, vr1;
    auto load_kv = [&](int c) {
        int j0 = c * 64;
        int tokk = (w * 1024 + j0 + jr + shift) & NMASK;
        const uint4* p = (const uint4*)(qkv + (long)tokk * 1536 + 512 + hh * 64 + qf * 16);
        kr0 = p[0];
        kr1 = p[1];
        int t0 = (w * 1024 + j0 + 2 * jp + shift) & NMASK;
        int t1 = (w * 1024 + j0 + 2 * jp + 1 + shift) & NMASK;
        vr0 = *(const uint4*)(qkv + (long)t0 * 1536 + 1024 + hh * 64 + dg * 8);
        vr1 = *(const uint4*)(qkv + (long)t1 * 1536 + 1024 + hh * 64 + dg * 8);
    };

    load_kv(0);

    uint32_t accO[8][2];  // f16x2: [nt][row g | row g+8]
#pragma unroll
    for (int i = 0; i < 8; i++) { accO[i][0] = 0u; accO[i][1] = 0u; }
    float m0 = -1e30f, m1 = -1e30f, l0 = 0.f, l1 = 0.f;

    for (int c = 0; c < 16; c++) {
        __syncthreads();
        {
            int wo = jr * 36 + qf * 8;
            *(uint4*)&Ks[wo] = kr0;
            *(uint4*)&Ks[wo + 4] = kr1;
        }
        {
            const half_t* a0 = (const half_t*)&vr0;
            const half_t* a1 = (const half_t*)&vr1;
#pragma unroll
            for (int i = 0; i < 8; i++) {
                uint32_t pv;
                ((half_t*)&pv)[0] = a0[i];
                ((half_t*)&pv)[1] = a1[i];
                Vs[(dg * 8 + i) * 36 + jp] = pv;
            }
        }
        __syncthreads();

        if (c + 1 < 16) load_kv(c + 1);

        // ---- S = Q K^T (16x64 per warp), f16 accumulate ----
        uint32_t sc[8][2];
#pragma unroll
        for (int i = 0; i < 8; i++) { sc[i][0] = 0u; sc[i][1] = 0u; }
#pragma unroll
        for (int ks = 0; ks < 4; ks++) {
            uint32_t a[4];
            LDSM4(a[0], a[1], a[2], a[3], q_ad + ks * 32);
#pragma unroll
            for (int j = 0; j < 4; j++) {
                uint32_t b[4];
                LDSM4(b[0], b[1], b[2], b[3], k_ad + (uint32_t)(j * 16 * 144) + ks * 32);
                MMA16816H(sc[2 * j][0], sc[2 * j][1], a, b[0], b[1]);
                MMA16816H(sc[2 * j + 1][0], sc[2 * j + 1][1], a, b[2], b[3]);
            }
        }

        // ---- online softmax (stats fp32) ----
        float se[8][4];
#pragma unroll
        for (int nt = 0; nt < 8; nt++) {
            float2 u0 = unpack2(sc[nt][0]);
            float2 u1 = unpack2(sc[nt][1]);
            se[nt][0] = u0.x; se[nt][1] = u0.y;
            se[nt][2] = u1.x; se[nt][3] = u1.y;
        }
        float ml0 = -1e30f, ml1 = -1e30f;
#pragma unroll
        for (int nt = 0; nt < 8; nt++) {
            ml0 = fmaxf(ml0, fmaxf(se[nt][0], se[nt][1]));
            ml1 = fmaxf(ml1, fmaxf(se[nt][2], se[nt][3]));
        }
#pragma unroll
        for (int off = 1; off < 4; off <<= 1) {
            ml0 = fmaxf(ml0, __shfl_xor_sync(0xffffffffu, ml0, off));
            ml1 = fmaxf(ml1, __shfl_xor_sync(0xffffffffu, ml1, off));
        }
        float mn0 = fmaxf(m0, ml0), mn1 = fmaxf(m1, ml1);
        // apply alpha at fp16 precision to BOTH l and accO (bias cancels in O/l)
        __half ah0 = __float2half_rn(__expf(m0 - mn0));
        __half ah1 = __float2half_rn(__expf(m1 - mn1));
        float alpha0 = __half2float(ah0), alpha1 = __half2float(ah1);
        m0 = mn0; m1 = mn1;
        float rs0 = 0.f, rs1 = 0.f;
#pragma unroll
        for (int nt = 0; nt < 8; nt++) {
            float e0 = __expf(se[nt][0] - mn0);
            float e1 = __expf(se[nt][1] - mn0);
            float e2 = __expf(se[nt][2] - mn1);
            float e3 = __expf(se[nt][3] - mn1);
            rs0 += e0 + e1;
            rs1 += e2 + e3;
            sc[nt][0] = pack2(e0, e1);   // P back into f16 A-frag layout
            sc[nt][1] = pack2(e2, e3);
        }
#pragma unroll
        for (int off = 1; off < 4; off <<= 1) {
            rs0 += __shfl_xor_sync(0xffffffffu, rs0, off);
            rs1 += __shfl_xor_sync(0xffffffffu, rs1, off);
        }
        l0 = l0 * alpha0 + rs0;
        l1 = l1 * alpha1 + rs1;
        __half2 al0 = __half2half2(ah0), al1 = __half2half2(ah1);
#pragma unroll
        for (int nt = 0; nt < 8; nt++) {
            __half2 o0 = __hmul2(*(__half2*)&accO[nt][0], al0);
            __half2 o1 = __hmul2(*(__half2*)&accO[nt][1], al1);
            accO[nt][0] = *(uint32_t*)&o0;
            accO[nt][1] = *(uint32_t*)&o1;
        }

        // ---- O += P V (P already in frag layout; V via ldmatrix) ----
#pragma unroll
        for (int kt = 0; kt < 4; kt++) {
            uint32_t p[4];
            p[0] = sc[2 * kt][0];
            p[1] = sc[2 * kt][1];
            p[2] = sc[2 * kt + 1][0];
            p[3] = sc[2 * kt + 1][1];
#pragma unroll
            for (int j = 0; j < 4; j++) {
                uint32_t b[4];
                LDSM4(b[0], b[1], b[2], b[3], v_ad + (uint32_t)(j * 16 * 144) + kt * 32);
                MMA16816H(accO[2 * j][0], accO[2 * j][1], p, b[0], b[1]);
                MMA16816H(accO[2 * j + 1][0], accO[2 * j + 1][1], p, b[2], b[3]);
            }
        }
    }

    // ---- finalize + write ----
    float inv0 = 1.0f / l0, inv1 = 1.0f / l1;
    int tokA = (qbase + r0 + g + shift) & NMASK;
    int tokB = (qbase + r0 + g + 8 + shift) & NMASK;
#pragma unroll
    for (int nt = 0; nt < 8; nt++) {
        int col = hh * 64 + nt * 8 + 2 * t;
        float2 u0 = unpack2(accO[nt][0]);
        float2 u1 = unpack2(accO[nt][1]);
        *(uint32_t*)(attn + (long)tokA * CDIM + col) = pack2(u0.x * inv0, u0.y * inv0);
        *(uint32_t*)(attn + (long)tokB * CDIM + col) = pack2(u1.x * inv1, u1.y * inv1);
    }
}

// ---------------- input embed ------------------------------------------------
__global__ void k_init(const float* __restrict__ feats, const int* __restrict__ coords,
                       const float* __restrict__ in_w, const float* __restrict__ in_b,
                       float* __restrict__ h) {
    int n = blockIdx.x;
    int tid = threadIdx.x;  // 256
    __shared__ float f[8];
    __shared__ int cd[3];
    if (tid < 8) f[tid] = feats[n * 8 + tid];
    if (tid < 3) cd[tid] = coords[n * 3 + tid];
    __syncthreads();
    for (int c = tid; c < CDIM; c += 256) {
        float acc = in_b[c];
#pragma unroll
        for (int i = 0; i < 8; i++) acc += f[i] * in_w[c * 8 + i];
        if (c < 510) {
            int j = c / 170;
            int k = c - j * 170;
            int kk = (k < 85) ? k : k - 85;
            float freq = expf((float)kk * (-9.210340371976184f / 85.0f));
            float o = (float)cd[j] * freq;
            acc += (k < 85) ? sinf(o) : cosf(o);
        }
        h[(long)n * CDIM + c] = acc;
    }
}

// ---------------- t embedding -> silu(c) ------------------------------------
__global__ void k_tembed(const float* __restrict__ t,
                         const float* __restrict__ w1, const float* __restrict__ b1,
                         const float* __restrict__ w2, const float* __restrict__ b2,
                         float* __restrict__ siluc) {
    __shared__ float emb[256];
    __shared__ float hid[512];
    int tid = threadIdx.x;  // 256
    float tv = t[0];
    if (tid < 128) {
        float fr = expf((float)tid * (-9.210340371976184f / 128.0f));
        float a = tv * fr;
        emb[tid] = cosf(a);
        emb[128 + tid] = sinf(a);
    }
    __syncthreads();
    for (int c = tid; c < 512; c += 256) {
        float acc = b1[c];
        const float* wr = w1 + (long)c * 256;
        for (int k = 0; k < 256; k++) acc += emb[k] * wr[k];
        hid[c] = acc / (1.0f + expf(-acc));
    }
    __syncthreads();
    for (int c = tid; c < 512; c += 256) {
        float acc = b2[c];
        const float* wr = w2 + (long)c * 512;
        for (int k = 0; k < 512; k++) acc += hid[k] * wr[k];
        siluc[c] = acc / (1.0f + expf(-acc));
    }
}

// ---------------- adaLN modulation: ALL 8 layers in one launch ---------------
__global__ void k_ada(const float* __restrict__ siluc, const float* __restrict__ ada_w,
                      const float* __restrict__ ada_b, float* __restrict__ mod) {
    __shared__ float sc[512];
    int tid = threadIdx.x;  // 256
    for (int c = tid; c < 512; c += 256) sc[c] = siluc[c];
    __syncthreads();
    int warp = tid >> 5, lane = tid & 31;
    int m = blockIdx.x * 8 + warp;  // 0..24575
    const float* wr = ada_w + (long)m * 512;
    float acc = 0.f;
    for (int k = lane; k < 512; k += 32) acc += sc[k] * wr[k];
#pragma unroll
    for (int off = 16; off; off >>= 1) acc += __shfl_xor_sync(0xffffffffu, acc, off);
    if (lane == 0) mod[m] = acc + ada_b[m];
}

// ---------------- LN + modulation -> fp16 ------------------------------------
__global__ void k_modln(const float* __restrict__ h, half_t* __restrict__ hn,
                        const float* __restrict__ mod, int sc_off, int sm_off) {
    int n = blockIdx.x;
    int tid = threadIdx.x;  // 128
    const float4* hp = (const float4*)(h + (long)n * CDIM);
    float4 x = hp[tid];
    float s = x.x + x.y + x.z + x.w;
    float sq = x.x * x.x + x.y * x.y + x.z * x.z + x.w * x.w;
#pragma unroll
    for (int off = 16; off; off >>= 1) {
        s += __shfl_xor_sync(0xffffffffu, s, off);
        sq += __shfl_xor_sync(0xffffffffu, sq, off);
    }
    __shared__ float rs[4], rq[4];
    int warp = tid >> 5;
    if ((tid & 31) == 0) { rs[warp] = s; rq[warp] = sq; }
    __syncthreads();
    float S = rs[0] + rs[1] + rs[2] + rs[3];
    float SQ = rq[0] + rq[1] + rq[2] + rq[3];
    float mean = S * (1.0f / 512.0f);
    float var = SQ * (1.0f / 512.0f) - mean * mean;
    float inv = rsqrtf(var + 1e-6f);
    int c = tid * 4;
    float4 scv = *(const float4*)(mod + sc_off + c);
    float4 smv = *(const float4*)(mod + sm_off + c);
    float o0 = (x.x - mean) * inv * (1.0f + scv.x) + smv.x;
    float o1 = (x.y - mean) * inv * (1.0f + scv.y) + smv.y;
    float o2 = (x.z - mean) * inv * (1.0f + scv.z) + smv.z;
    float o3 = (x.w - mean) * inv * (1.0f + scv.w) + smv.w;
    uint2 o;
    o.x = pack2(o0, o1);
    o.y = pack2(o2, o3);
    *(uint2*)(hn + (long)n * CDIM + c) = o;
}

// ---------------- output head ------------------------------------------------
__global__ void k_final(const float* __restrict__ h, const float* __restrict__ out_w,
                        const float* __restrict__ out_b, float* __restrict__ out) {
    int warp = threadIdx.x >> 5, lane = threadIdx.x & 31;
    int n = blockIdx.x * 8 + warp;
    const float* hp = h + (long)n * CDIM;
    float acc[8];
#pragma unroll
    for (int o = 0; o < 8; o++) acc[o] = 0.f;
    for (int c = lane; c < CDIM; c += 32) {
        float hv = hp[c];
#pragma unroll
        for (int o = 0; o < 8; o++) acc[o] += hv * out_w[o * CDIM + c];
    }
#pragma unroll
    for (int off = 16; off; off >>= 1)
#pragma unroll
        for (int o = 0; o < 8; o++) acc[o] += __shfl_xor_sync(0xffffffffu, acc[o], off);
    if (lane == 0)
#pragma unroll
        for (int o = 0; o < 8; o++) out[(long)n * 8 + o] = acc[o] + out_b[o];
}

// ---------------- launch ----------------------------------------------------
extern "C" void kernel_launch(void* const* d_in, const int* in_sizes, int n_in,
                              void* d_out, int out_size) {
    const float* feats  = (const float*)d_in[0];
    const int*   coords = (const int*)d_in[1];
    const float* t      = (const float*)d_in[2];
    const float* in_w   = (const float*)d_in[3];
    const float* in_b   = (const float*)d_in[4];
    const float* t_w1   = (const float*)d_in[5];
    const float* t_b1   = (const float*)d_in[6];
    const float* t_w2   = (const float*)d_in[7];
    const float* t_b2   = (const float*)d_in[8];
    const float* qkv_w  = (const float*)d_in[9];
    const float* qkv_b  = (const float*)d_in[10];
    const float* proj_w = (const float*)d_in[11];
    const float* proj_b = (const float*)d_in[12];
    const float* ada_w  = (const float*)d_in[13];
    const float* ada_b  = (const float*)d_in[14];
    const float* fc1_w  = (const float*)d_in[15];
    const float* fc1_b  = (const float*)d_in[16];
    const float* fc2_w  = (const float*)d_in[17];
    const float* fc2_b  = (const float*)d_in[18];
    const float* out_w  = (const float*)d_in[19];
    const float* out_b  = (const float*)d_in[20];
    float* out = (float*)d_out;

    float *p_h, *p_mod, *p_siluc;
    half_t *p_hn, *p_q, *p_a, *p_m, *p_w;
    cudaGetSymbolAddress((void**)&p_h, g_h);
    cudaGetSymbolAddress((void**)&p_mod, g_mod);
    cudaGetSymbolAddress((void**)&p_siluc, g_siluc);
    cudaGetSymbolAddress((void**)&p_hn, g_hn);
    cudaGetSymbolAddress((void**)&p_q, g_qkv);
    cudaGetSymbolAddress((void**)&p_a, g_attn);
    cudaGetSymbolAddress((void**)&p_m, g_mlp);
    cudaGetSymbolAddress((void**)&p_w, g_w);

    const int GSM = 61440;  // 3 stages x 20480B
    const int ASM = 36864;  // Q 4608 + K 2304 + V 2304 words
    cudaFuncSetAttribute(k_mma_gemm<0>, cudaFuncAttributeMaxDynamicSharedMemorySize, GSM);
    cudaFuncSetAttribute(k_mma_gemm<1>, cudaFuncAttributeMaxDynamicSharedMemorySize, GSM);
    cudaFuncSetAttribute(k_mma_gemm<2>, cudaFuncAttributeMaxDynamicSharedMemorySize, GSM);
    cudaFuncSetAttribute(k_attn_mma, cudaFuncAttributeMaxDynamicSharedMemorySize, ASM);

    // weight fp16 conversion — single launch covering all 4 tensors
    k_half_all<<<24576, 256>>>(qkv_w, proj_w, fc1_w, fc2_w, p_w);

    k_init<<<NTOK, 256>>>(feats, coords, in_w, in_b, p_h);
    k_tembed<<<1, 256>>>(t, t_w1, t_b1, t_w2, t_b2, p_siluc);
    // all 8 layers' adaLN modulation upfront (loop-invariant)
    k_ada<<<3072, 256>>>(p_siluc, ada_w, ada_b, p_mod);

    for (int i = 0; i < 8; i++) {
        int shift = (i & 1) * 512;
        const float* mod_i = p_mod + i * 3072;
        // attention branch
        k_modln<<<NTOK, 128>>>(p_h, p_hn, mod_i, 512, 0);
        k_mma_gemm<0><<<dim3(12, 128), 256, GSM>>>(
            p_hn, p_w + OFF_QKV + (long)i * 786432, qkv_b + (long)i * 1536,
            nullptr, p_q, nullptr, 512, 1536);
        k_attn_mma<<<dim3(8, 8, 16), 256, ASM>>>(p_q, p_a, shift);
        k_mma_gemm<2><<<dim3(4, 128), 256, GSM>>>(
            p_a, p_w + OFF_PROJ + (long)i * 262144, proj_b + (long)i * 512,
            p_h, nullptr, mod_i + 1024, 512, 512);
        // mlp branch
        k_modln<<<NTOK, 128>>>(p_h, p_hn, mod_i, 2048, 1536);
        k_mma_gemm<1><<<dim3(16, 128), 256, GSM>>>(
            p_hn, p_w + OFF_FC1 + (long)i * 1048576, fc1_b + (long)i * 2048,
            nullptr, p_m, nullptr, 512, 2048);
        k_mma_gemm<2><<<dim3(4, 128), 256, GSM>>>(
            p_m, p_w + OFF_FC2 + (long)i * 1048576, fc2_b + (long)i * 512,
            p_h, nullptr, mod_i + 2560, 2048, 512);
    }

    k_final<<<2048, 256>>>(p_h, out_w, out_b, out);
}

// round 17
// speedup vs baseline: 1.1158x; 1.0759x over previous
#include <cuda_runtime.h>
#include <cuda_fp16.h>
#include <math.h>
#include <stdint.h>

#define NTOK 16384
#define NMASK 16383
#define CDIM 512
#define CFFD 2048

typedef __half half_t;

// ---------------- scratch (static device globals; no allocs) ----------------
__device__ float g_h[NTOK * CDIM];
__device__ float g_mod[8 * 3072];   // all 8 layers' adaLN modulation
__device__ float g_siluc[CDIM];
__device__ half_t g_hn[NTOK * CDIM];
__device__ half_t g_qkv[NTOK * 3 * CDIM];
__device__ half_t g_attn[NTOK * CDIM];
__device__ half_t g_mlp[NTOK * CFFD];
// weights fp16: [qkv | proj | fc1 | fc2]
#define OFF_QKV 0
#define OFF_PROJ 6291456
#define OFF_FC1 8388608
#define OFF_FC2 16777216
__device__ half_t g_w[25165824];

// ======================= helpers ============================================
// fp16-accumulate mma: D,C are 2 regs of f16x2 (row g | row g+8)
#define MMA16816H(c0, c1, a, b0v, b1v)                                          \
    asm volatile(                                                               \
        "mma.sync.aligned.m16n8k16.row.col.f16.f16.f16.f16 "                    \
        "{%0,%1},{%2,%3,%4,%5},{%6,%7},{%0,%1};"                                \
        : "+r"(c0), "+r"(c1)                                                    \
        : "r"((a)[0]), "r"((a)[1]), "r"((a)[2]), "r"((a)[3]), "r"(b0v), "r"(b1v))

#define LDSM4(r0, r1, r2, r3, addr)                                             \
    asm volatile("ldmatrix.sync.aligned.m8n8.x4.shared.b16 {%0,%1,%2,%3}, [%4];" \
        : "=r"(r0), "=r"(r1), "=r"(r2), "=r"(r3) : "r"(addr))

#define CP_ASYNC16(dst_u32, src_ptr) \
    asm volatile("cp.async.cg.shared.global [%0], [%1], 16;" :: "r"(dst_u32), "l"(src_ptr))
#define CP_COMMIT() asm volatile("cp.async.commit_group;")
#define CP_WAIT1() asm volatile("cp.async.wait_group 1;")

__device__ __forceinline__ uint32_t smem_u32(const void* p) {
    uint32_t a;
    asm("{ .reg .u64 t; cvta.to.shared.u64 t, %1; cvt.u32.u64 %0, t; }" : "=r"(a) : "l"(p));
    return a;
}

__device__ __forceinline__ uint32_t pack2(float a, float b) {
    __half2 h = __floats2half2_rn(a, b);
    return *(uint32_t*)&h;
}
__device__ __forceinline__ float2 unpack2(uint32_t v) {
    __half2 h = *(__half2*)&v;
    return make_float2(__half2float(h.x), __half2float(h.y));
}

// fp32 -> fp16 conversion, all 4 weight tensors in ONE launch.
__global__ void k_half_all(const float* __restrict__ s_qkv, const float* __restrict__ s_proj,
                           const float* __restrict__ s_fc1, const float* __restrict__ s_fc2,
                           half_t* __restrict__ dst) {
    int b = blockIdx.x;
    const float* src;
    half_t* d;
    if (b < 6144) {
        src = s_qkv; d = dst + OFF_QKV;
    } else if (b < 8192) {
        src = s_proj; d = dst + OFF_PROJ; b -= 6144;
    } else if (b < 16384) {
        src = s_fc1; d = dst + OFF_FC1; b -= 8192;
    } else {
        src = s_fc2; d = dst + OFF_FC2; b -= 16384;
    }
    int i = b * 256 + threadIdx.x;
    float4 v = ((const float4*)src)[i];
    uint2 o;
    o.x = pack2(v.x, v.y);
    o.y = pack2(v.z, v.w);
    ((uint2*)d)[i] = o;
}

// ======================= fp16 HMMA GEMM (128x256 tile, f16 acc) =============
// out(NxM) = A(NxK) @ W(MxK)^T; fp16 operands AND accumulators.
// CTA 128 rows x 256 cols, BK=32, 8 warps (2x4), warp tile 64x64, 2 CTAs/SM.
// smem stage: A 128x40h (10240B) + B 256x40h (20480B) = 30720B; 3 stages.
// EPI 0: half-write (qkv; scale 0.125 on cols<512)
// EPI 1: gelu then half-write
// EPI 2: outf += gate[col]*(acc+bias)   (fp32 RMW)
template <int EPI>
__global__ void __launch_bounds__(256, 2)
k_mma_gemm(const half_t* __restrict__ A, const half_t* __restrict__ W,
           const float* __restrict__ bias, float* __restrict__ outf,
           half_t* __restrict__ oh, const float* __restrict__ gate, int K, int M) {
    extern __shared__ uint32_t smw[];  // 3 stages x 7680 words = 92160B

    const int tid = threadIdx.x;
    const int wid = tid >> 5;
    const int lane = tid & 31;
    const int g = lane >> 2;
    const int t = lane & 3;
    const int warp_m = wid >> 2;   // 0..1
    const int warp_n = wid & 3;    // 0..3
    const int lq = lane >> 3, lr = lane & 7;

    const int m0 = blockIdx.y * 128;
    const int n0 = blockIdx.x * 256;

    const half_t* Ap = A + (long)m0 * K;
    const half_t* Bp = W + (long)n0 * K;
    const int NC = K >> 5;

    const uint32_t sbase = smem_u32(smw);
    const int cr = tid >> 2, cq = tid & 3;

    // ldmatrix per-lane role constants
    const int a_row = warp_m * 64 + lr + ((lq & 1) << 3);  // + mt*16
    const int a_koff = (lq >> 1) << 2;                     // + ks*8
    const int b_col = warp_n * 64 + ((lq >> 1) << 3) + lr; // + j*16
    const int b_koff = (lq & 1) << 2;                      // + ks*8

    uint32_t acc[4][8][2];  // f16x2 accumulators: [mt][nt][row g | row g+8]
#pragma unroll
    for (int i = 0; i < 4; i++)
#pragma unroll
        for (int j = 0; j < 8; j++) { acc[i][j][0] = 0u; acc[i][j][1] = 0u; }

    // stage layout: A at +0 (2560 words), B at +2560 (5120 words)
    auto cp_chunk = [&](int c, int s) {
        uint32_t st = sbase + s * 30720;
#pragma unroll
        for (int it = 0; it < 2; it++) {      // A: 128 rows
            int r = cr + it * 64;
            long go = (long)r * K + c * 32 + cq * 8;
            CP_ASYNC16(st + (uint32_t)(r * 80 + cq * 16), Ap + go);
        }
#pragma unroll
        for (int it = 0; it < 4; it++) {      // B: 256 rows
            int r = cr + it * 64;
            long go = (long)r * K + c * 32 + cq * 8;
            CP_ASYNC16(st + 10240 + (uint32_t)(r * 80 + cq * 16), Bp + go);
        }
    };

    auto compute = [&](int s) {
        uint32_t stA = sbase + s * 30720;
        uint32_t stB = stA + 10240;
#pragma unroll
        for (int ks = 0; ks < 2; ks++) {
            uint32_t a[4][4], b[8][2];
#pragma unroll
            for (int mt = 0; mt < 4; mt++) {
                uint32_t ad = stA + (uint32_t)(((a_row + mt * 16) * 20 + a_koff + ks * 8) * 4);
                LDSM4(a[mt][0], a[mt][1], a[mt][2], a[mt][3], ad);
            }
#pragma unroll
            for (int j = 0; j < 4; j++) {
                uint32_t bd = stB + (uint32_t)(((b_col + j * 16) * 20 + b_koff + ks * 8) * 4);
                LDSM4(b[2 * j][0], b[2 * j][1], b[2 * j + 1][0], b[2 * j + 1][1], bd);
            }
#pragma unroll
            for (int nt = 0; nt < 8; nt++)
#pragma unroll
                for (int mt = 0; mt < 4; mt++)
                    MMA16816H(acc[mt][nt][0], acc[mt][nt][1], a[mt], b[nt][0], b[nt][1]);
        }
    };

    cp_chunk(0, 0); CP_COMMIT();
    cp_chunk(1, 1); CP_COMMIT();

    int s_next = 2, s_cur = 0;
    for (int c = 0; c < NC; c++) {
        CP_WAIT1();
        __syncthreads();
        if (c + 2 < NC) cp_chunk(c + 2, s_next);
        CP_COMMIT();
        compute(s_cur);
        s_cur = (s_cur == 2) ? 0 : s_cur + 1;
        s_next = (s_next == 2) ? 0 : s_next + 1;
    }

    // ---- epilogue (fp32 math on unpacked accumulators) ----
#pragma unroll
    for (int mt = 0; mt < 4; mt++) {
#pragma unroll
        for (int nt = 0; nt < 8; nt++) {
            float2 u0 = unpack2(acc[mt][nt][0]);
            float2 u1 = unpack2(acc[mt][nt][1]);
            int row = m0 + warp_m * 64 + mt * 16 + g;
            int col = n0 + warp_n * 64 + nt * 8 + 2 * t;
            float b0 = __ldg(bias + col), b1 = __ldg(bias + col + 1);
            float v[4];
            v[0] = u0.x + b0; v[1] = u0.y + b1;
            v[2] = u1.x + b0; v[3] = u1.y + b1;
            if (EPI == 0) {
                if (col < 512) {
#pragma unroll
                    for (int e = 0; e < 4; e++) v[e] *= 0.125f;
                }
            }
            if (EPI == 1) {
#pragma unroll
                for (int e = 0; e < 4; e++) {
                    float x = v[e];
                    float x3 = x * x * x;
                    v[e] = 0.5f * x * (1.0f + tanhf(0.7978845608028654f * (x + 0.044715f * x3)));
                }
            }
            if (EPI == 2) {
                float* dp0 = outf + (long)row * M + col;
                float* dp1 = outf + (long)(row + 8) * M + col;
                float g0 = __ldg(gate + col), g1 = __ldg(gate + col + 1);
                float2 o0 = *(float2*)dp0;
                float2 o1 = *(float2*)dp1;
                o0.x += g0 * v[0]; o0.y += g1 * v[1];
                o1.x += g0 * v[2]; o1.y += g1 * v[3];
                *(float2*)dp0 = o0;
                *(float2*)dp1 = o1;
            } else {
                *(uint32_t*)(oh + (long)row * M + col) = pack2(v[0], v[1]);
                *(uint32_t*)(oh + (long)(row + 8) * M + col) = pack2(v[2], v[3]);
            }
        }
    }
}

// ======================= fp16 HMMA windowed flash attention =================
// grid (qtile=8, head=8, window=16), 256 thr (8 warps), BQ=128, BKV=64, D=64.
// q pre-scaled by 0.125 at the qkv epilogue. f16 accumulators for S and O;
// softmax stats fp32; alpha applied at fp16 to both l and accO (bias cancels).
__global__ void __launch_bounds__(256, 1)
k_attn_mma(const half_t* __restrict__ qkv, half_t* __restrict__ attn, int shift) {
    extern __shared__ uint32_t sw[];
    uint32_t* Qs = sw;            // 128 rows x 36 words (72 half pitch)
    uint32_t* Ks = Qs + 4608;     // 64 rows x 36 words
    uint32_t* Vs = Ks + 2304;     // 64 d-rows x 36 words (token-pair packed)

    const int tid = threadIdx.x;
    const int wid = tid >> 5;
    const int lane = tid & 31;
    const int g = lane >> 2;
    const int t = tid & 3;

    const int lq = lane >> 3, lr = lane & 7;

    const int qt = blockIdx.x, hh = blockIdx.y, w = blockIdx.z;
    const int qbase = w * 1024 + qt * 128;
    const int r0 = wid * 16;

    const uint32_t sbase = smem_u32(sw);
    const uint32_t q_ad = sbase + (uint32_t)(((r0 + lr + ((lane & 8) ? 8 : 0)) * 36 + ((lq >> 1) << 2)) * 4);
    const uint32_t kv_row = (uint32_t)((((lq >> 1) << 3) + lr) * 36 + ((lq & 1) << 2)) * 4;
    const uint32_t k_ad = sbase + 18432 + kv_row;
    const uint32_t v_ad = sbase + 27648 + kv_row;

    const int jr = tid >> 2, qf = tid & 3;
    const int jp = tid & 31, dg = tid >> 5;

    // ---- load Q tile ----
    {
        int row = tid >> 1, hf = tid & 1;
        int tok = (qbase + row + shift) & NMASK;
        const uint4* p = (const uint4*)(qkv + (long)tok * 1536 + hh * 64 + hf * 32);
        int wo = row * 36 + hf * 16;
#pragma unroll
        for (int q = 0; q < 4; q++) *(uint4*)&Qs[wo + q * 4] = p[q];
    }

    uint4 kr0, kr1, vr0, vr1;
    auto load_kv = [&](int c) {
        int j0 = c * 64;
        int tokk = (w * 1024 + j0 + jr + shift) & NMASK;
        const uint4* p = (const uint4*)(qkv + (long)tokk * 1536 + 512 + hh * 64 + qf * 16);
        kr0 = p[0];
        kr1 = p[1];
        int t0 = (w * 1024 + j0 + 2 * jp + shift) & NMASK;
        int t1 = (w * 1024 + j0 + 2 * jp + 1 + shift) & NMASK;
        vr0 = *(const uint4*)(qkv + (long)t0 * 1536 + 1024 + hh * 64 + dg * 8);
        vr1 = *(const uint4*)(qkv + (long)t1 * 1536 + 1024 + hh * 64 + dg * 8);
    };

    load_kv(0);

    uint32_t accO[8][2];
#pragma unroll
    for (int i = 0; i < 8; i++) { accO[i][0] = 0u; accO[i][1] = 0u; }
    float m0 = -1e30f, m1 = -1e30f, l0 = 0.f, l1 = 0.f;

    for (int c = 0; c < 16; c++) {
        __syncthreads();
        {
            int wo = jr * 36 + qf * 8;
            *(uint4*)&Ks[wo] = kr0;
            *(uint4*)&Ks[wo + 4] = kr1;
        }
        {
            const half_t* a0 = (const half_t*)&vr0;
            const half_t* a1 = (const half_t*)&vr1;
#pragma unroll
            for (int i = 0; i < 8; i++) {
                uint32_t pv;
                ((half_t*)&pv)[0] = a0[i];
                ((half_t*)&pv)[1] = a1[i];
                Vs[(dg * 8 + i) * 36 + jp] = pv;
            }
        }
        __syncthreads();

        if (c + 1 < 16) load_kv(c + 1);

        // ---- S = Q K^T (16x64 per warp), f16 accumulate ----
        uint32_t sc[8][2];
#pragma unroll
        for (int i = 0; i < 8; i++) { sc[i][0] = 0u; sc[i][1] = 0u; }
#pragma unroll
        for (int ks = 0; ks < 4; ks++) {
            uint32_t a[4];
            LDSM4(a[0], a[1], a[2], a[3], q_ad + ks * 32);
#pragma unroll
            for (int j = 0; j < 4; j++) {
                uint32_t b[4];
                LDSM4(b[0], b[1], b[2], b[3], k_ad + (uint32_t)(j * 16 * 144) + ks * 32);
                MMA16816H(sc[2 * j][0], sc[2 * j][1], a, b[0], b[1]);
                MMA16816H(sc[2 * j + 1][0], sc[2 * j + 1][1], a, b[2], b[3]);
            }
        }

        // ---- online softmax (stats fp32) ----
        float se[8][4];
#pragma unroll
        for (int nt = 0; nt < 8; nt++) {
            float2 u0 = unpack2(sc[nt][0]);
            float2 u1 = unpack2(sc[nt][1]);
            se[nt][0] = u0.x; se[nt][1] = u0.y;
            se[nt][2] = u1.x; se[nt][3] = u1.y;
        }
        float ml0 = -1e30f, ml1 = -1e30f;
#pragma unroll
        for (int nt = 0; nt < 8; nt++) {
            ml0 = fmaxf(ml0, fmaxf(se[nt][0], se[nt][1]));
            ml1 = fmaxf(ml1, fmaxf(se[nt][2], se[nt][3]));
        }
#pragma unroll
        for (int off = 1; off < 4; off <<= 1) {
            ml0 = fmaxf(ml0, __shfl_xor_sync(0xffffffffu, ml0, off));
            ml1 = fmaxf(ml1, __shfl_xor_sync(0xffffffffu, ml1, off));
        }
        float mn0 = fmaxf(m0, ml0), mn1 = fmaxf(m1, ml1);
        __half ah0 = __float2half_rn(__expf(m0 - mn0));
        __half ah1 = __float2half_rn(__expf(m1 - mn1));
        float alpha0 = __half2float(ah0), alpha1 = __half2float(ah1);
        m0 = mn0; m1 = mn1;
        float rs0 = 0.f, rs1 = 0.f;
#pragma unroll
        for (int nt = 0; nt < 8; nt++) {
            float e0 = __expf(se[nt][0] - mn0);
            float e1 = __expf(se[nt][1] - mn0);
            float e2 = __expf(se[nt][2] - mn1);
            float e3 = __expf(se[nt][3] - mn1);
            rs0 += e0 + e1;
            rs1 += e2 + e3;
            sc[nt][0] = pack2(e0, e1);
            sc[nt][1] = pack2(e2, e3);
        }
#pragma unroll
        for (int off = 1; off < 4; off <<= 1) {
            rs0 += __shfl_xor_sync(0xffffffffu, rs0, off);
            rs1 += __shfl_xor_sync(0xffffffffu, rs1, off);
        }
        l0 = l0 * alpha0 + rs0;
        l1 = l1 * alpha1 + rs1;
        __half2 al0 = __half2half2(ah0), al1 = __half2half2(ah1);
#pragma unroll
        for (int nt = 0; nt < 8; nt++) {
            __half2 o0 = __hmul2(*(__half2*)&accO[nt][0], al0);
            __half2 o1 = __hmul2(*(__half2*)&accO[nt][1], al1);
            accO[nt][0] = *(uint32_t*)&o0;
            accO[nt][1] = *(uint32_t*)&o1;
        }

        // ---- O += P V ----
#pragma unroll
        for (int kt = 0; kt < 4; kt++) {
            uint32_t p[4];
            p[0] = sc[2 * kt][0];
            p[1] = sc[2 * kt][1];
            p[2] = sc[2 * kt + 1][0];
            p[3] = sc[2 * kt + 1][1];
#pragma unroll
            for (int j = 0; j < 4; j++) {
                uint32_t b[4];
                LDSM4(b[0], b[1], b[2], b[3], v_ad + (uint32_t)(j * 16 * 144) + kt * 32);
                MMA16816H(accO[2 * j][0], accO[2 * j][1], p, b[0], b[1]);
                MMA16816H(accO[2 * j + 1][0], accO[2 * j + 1][1], p, b[2], b[3]);
            }
        }
    }

    // ---- finalize + write ----
    float inv0 = 1.0f / l0, inv1 = 1.0f / l1;
    int tokA = (qbase + r0 + g + shift) & NMASK;
    int tokB = (qbase + r0 + g + 8 + shift) & NMASK;
#pragma unroll
    for (int nt = 0; nt < 8; nt++) {
        int col = hh * 64 + nt * 8 + 2 * t;
        float2 u0 = unpack2(accO[nt][0]);
        float2 u1 = unpack2(accO[nt][1]);
        *(uint32_t*)(attn + (long)tokA * CDIM + col) = pack2(u0.x * inv0, u0.y * inv0);
        *(uint32_t*)(attn + (long)tokB * CDIM + col) = pack2(u1.x * inv1, u1.y * inv1);
    }
}

// ---------------- input embed ------------------------------------------------
__global__ void k_init(const float* __restrict__ feats, const int* __restrict__ coords,
                       const float* __restrict__ in_w, const float* __restrict__ in_b,
                       float* __restrict__ h) {
    int n = blockIdx.x;
    int tid = threadIdx.x;  // 256
    __shared__ float f[8];
    __shared__ int cd[3];
    if (tid < 8) f[tid] = feats[n * 8 + tid];
    if (tid < 3) cd[tid] = coords[n * 3 + tid];
    __syncthreads();
    for (int c = tid; c < CDIM; c += 256) {
        float acc = in_b[c];
#pragma unroll
        for (int i = 0; i < 8; i++) acc += f[i] * in_w[c * 8 + i];
        if (c < 510) {
            int j = c / 170;
            int k = c - j * 170;
            int kk = (k < 85) ? k : k - 85;
            float freq = expf((float)kk * (-9.210340371976184f / 85.0f));
            float o = (float)cd[j] * freq;
            acc += (k < 85) ? sinf(o) : cosf(o);
        }
        h[(long)n * CDIM + c] = acc;
    }
}

// ---------------- t embedding -> silu(c) ------------------------------------
__global__ void k_tembed(const float* __restrict__ t,
                         const float* __restrict__ w1, const float* __restrict__ b1,
                         const float* __restrict__ w2, const float* __restrict__ b2,
                         float* __restrict__ siluc) {
    __shared__ float emb[256];
    __shared__ float hid[512];
    int tid = threadIdx.x;  // 256
    float tv = t[0];
    if (tid < 128) {
        float fr = expf((float)tid * (-9.210340371976184f / 128.0f));
        float a = tv * fr;
        emb[tid] = cosf(a);
        emb[128 + tid] = sinf(a);
    }
    __syncthreads();
    for (int c = tid; c < 512; c += 256) {
        float acc = b1[c];
        const float* wr = w1 + (long)c * 256;
        for (int k = 0; k < 256; k++) acc += emb[k] * wr[k];
        hid[c] = acc / (1.0f + expf(-acc));
    }
    __syncthreads();
    for (int c = tid; c < 512; c += 256) {
        float acc = b2[c];
        const float* wr = w2 + (long)c * 512;
        for (int k = 0; k < 512; k++) acc += hid[k] * wr[k];
        siluc[c] = acc / (1.0f + expf(-acc));
    }
}

// ---------------- adaLN modulation: ALL 8 layers in one launch ---------------
__global__ void k_ada(const float* __restrict__ siluc, const float* __restrict__ ada_w,
                      const float* __restrict__ ada_b, float* __restrict__ mod) {
    __shared__ float sc[512];
    int tid = threadIdx.x;  // 256
    for (int c = tid; c < 512; c += 256) sc[c] = siluc[c];
    __syncthreads();
    int warp = tid >> 5, lane = tid & 31;
    int m = blockIdx.x * 8 + warp;  // 0..24575
    const float* wr = ada_w + (long)m * 512;
    float acc = 0.f;
    for (int k = lane; k < 512; k += 32) acc += sc[k] * wr[k];
#pragma unroll
    for (int off = 16; off; off >>= 1) acc += __shfl_xor_sync(0xffffffffu, acc, off);
    if (lane == 0) mod[m] = acc + ada_b[m];
}

// ---------------- LN + modulation -> fp16 ------------------------------------
__global__ void k_modln(const float* __restrict__ h, half_t* __restrict__ hn,
                        const float* __restrict__ mod, int sc_off, int sm_off) {
    int n = blockIdx.x;
    int tid = threadIdx.x;  // 128
    const float4* hp = (const float4*)(h + (long)n * CDIM);
    float4 x = hp[tid];
    float s = x.x + x.y + x.z + x.w;
    float sq = x.x * x.x + x.y * x.y + x.z * x.z + x.w * x.w;
#pragma unroll
    for (int off = 16; off; off >>= 1) {
        s += __shfl_xor_sync(0xffffffffu, s, off);
        sq += __shfl_xor_sync(0xffffffffu, sq, off);
    }
    __shared__ float rs[4], rq[4];
    int warp = tid >> 5;
    if ((tid & 31) == 0) { rs[warp] = s; rq[warp] = sq; }
    __syncthreads();
    float S = rs[0] + rs[1] + rs[2] + rs[3];
    float SQ = rq[0] + rq[1] + rq[2] + rq[3];
    float mean = S * (1.0f / 512.0f);
    float var = SQ * (1.0f / 512.0f) - mean * mean;
    float inv = rsqrtf(var + 1e-6f);
    int c = tid * 4;
    float4 scv = *(const float4*)(mod + sc_off + c);
    float4 smv = *(const float4*)(mod + sm_off + c);
    float o0 = (x.x - mean) * inv * (1.0f + scv.x) + smv.x;
    float o1 = (x.y - mean) * inv * (1.0f + scv.y) + smv.y;
    float o2 = (x.z - mean) * inv * (1.0f + scv.z) + smv.z;
    float o3 = (x.w - mean) * inv * (1.0f + scv.w) + smv.w;
    uint2 o;
    o.x = pack2(o0, o1);
    o.y = pack2(o2, o3);
    *(uint2*)(hn + (long)n * CDIM + c) = o;
}

// ---------------- output head ------------------------------------------------
__global__ void k_final(const float* __restrict__ h, const float* __restrict__ out_w,
                        const float* __restrict__ out_b, float* __restrict__ out) {
    int warp = threadIdx.x >> 5, lane = threadIdx.x & 31;
    int n = blockIdx.x * 8 + warp;
    const float* hp = h + (long)n * CDIM;
    float acc[8];
#pragma unroll
    for (int o = 0; o < 8; o++) acc[o] = 0.f;
    for (int c = lane; c < CDIM; c += 32) {
        float hv = hp[c];
#pragma unroll
        for (int o = 0; o < 8; o++) acc[o] += hv * out_w[o * CDIM + c];
    }
#pragma unroll
    for (int off = 16; off; off >>= 1)
#pragma unroll
        for (int o = 0; o < 8; o++) acc[o] += __shfl_xor_sync(0xffffffffu, acc[o], off);
    if (lane == 0)
#pragma unroll
        for (int o = 0; o < 8; o++) out[(long)n * 8 + o] = acc[o] + out_b[o];
}

// ---------------- launch ----------------------------------------------------
extern "C" void kernel_launch(void* const* d_in, const int* in_sizes, int n_in,
                              void* d_out, int out_size) {
    const float* feats  = (const float*)d_in[0];
    const int*   coords = (const int*)d_in[1];
    const float* t      = (const float*)d_in[2];
    const float* in_w   = (const float*)d_in[3];
    const float* in_b   = (const float*)d_in[4];
    const float* t_w1   = (const float*)d_in[5];
    const float* t_b1   = (const float*)d_in[6];
    const float* t_w2   = (const float*)d_in[7];
    const float* t_b2   = (const float*)d_in[8];
    const float* qkv_w  = (const float*)d_in[9];
    const float* qkv_b  = (const float*)d_in[10];
    const float* proj_w = (const float*)d_in[11];
    const float* proj_b = (const float*)d_in[12];
    const float* ada_w  = (const float*)d_in[13];
    const float* ada_b  = (const float*)d_in[14];
    const float* fc1_w  = (const float*)d_in[15];
    const float* fc1_b  = (const float*)d_in[16];
    const float* fc2_w  = (const float*)d_in[17];
    const float* fc2_b  = (const float*)d_in[18];
    const float* out_w  = (const float*)d_in[19];
    const float* out_b  = (const float*)d_in[20];
    float* out = (float*)d_out;

    float *p_h, *p_mod, *p_siluc;
    half_t *p_hn, *p_q, *p_a, *p_m, *p_w;
    cudaGetSymbolAddress((void**)&p_h, g_h);
    cudaGetSymbolAddress((void**)&p_mod, g_mod);
    cudaGetSymbolAddress((void**)&p_siluc, g_siluc);
    cudaGetSymbolAddress((void**)&p_hn, g_hn);
    cudaGetSymbolAddress((void**)&p_q, g_qkv);
    cudaGetSymbolAddress((void**)&p_a, g_attn);
    cudaGetSymbolAddress((void**)&p_m, g_mlp);
    cudaGetSymbolAddress((void**)&p_w, g_w);

    const int GSM = 92160;  // 3 stages x 30720B
    const int ASM = 36864;
    cudaFuncSetAttribute(k_mma_gemm<0>, cudaFuncAttributeMaxDynamicSharedMemorySize, GSM);
    cudaFuncSetAttribute(k_mma_gemm<1>, cudaFuncAttributeMaxDynamicSharedMemorySize, GSM);
    cudaFuncSetAttribute(k_mma_gemm<2>, cudaFuncAttributeMaxDynamicSharedMemorySize, GSM);
    cudaFuncSetAttribute(k_attn_mma, cudaFuncAttributeMaxDynamicSharedMemorySize, ASM);

    // weight fp16 conversion — single launch covering all 4 tensors
    k_half_all<<<24576, 256>>>(qkv_w, proj_w, fc1_w, fc2_w, p_w);

    k_init<<<NTOK, 256>>>(feats, coords, in_w, in_b, p_h);
    k_tembed<<<1, 256>>>(t, t_w1, t_b1, t_w2, t_b2, p_siluc);
    // all 8 layers' adaLN modulation upfront (loop-invariant)
    k_ada<<<3072, 256>>>(p_siluc, ada_w, ada_b, p_mod);

    for (int i = 0; i < 8; i++) {
        int shift = (i & 1) * 512;
        const float* mod_i = p_mod + i * 3072;
        // attention branch
        k_modln<<<NTOK, 128>>>(p_h, p_hn, mod_i, 512, 0);
        k_mma_gemm<0><<<dim3(6, 128), 256, GSM>>>(
            p_hn, p_w + OFF_QKV + (long)i * 786432, qkv_b + (long)i * 1536,
            nullptr, p_q, nullptr, 512, 1536);
        k_attn_mma<<<dim3(8, 8, 16), 256, ASM>>>(p_q, p_a, shift);
        k_mma_gemm<2><<<dim3(2, 128), 256, GSM>>>(
            p_a, p_w + OFF_PROJ + (long)i * 262144, proj_b + (long)i * 512,
            p_h, nullptr, mod_i + 1024, 512, 512);
        // mlp branch
        k_modln<<<NTOK, 128>>>(p_h, p_hn, mod_i, 2048, 1536);
        k_mma_gemm<1><<<dim3(8, 128), 256, GSM>>>(
            p_hn, p_w + OFF_FC1 + (long)i * 1048576, fc1_b + (long)i * 2048,
            nullptr, p_m, nullptr, 512, 2048);
        k_mma_gemm<2><<<dim3(2, 128), 256, GSM>>>(
            p_m, p_w + OFF_FC2 + (long)i * 1048576, fc2_b + (long)i * 512,
            p_h, nullptr, mod_i + 2560, 2048, 512);
    }

    k_final<<<2048, 256>>>(p_h, out_w, out_b, out);
}